// round 14
// baseline (speedup 1.0000x reference)
#include <cuda_runtime.h>
#include <cuda_bf16.h>

#define NBLK 128
#define NTHR 512
#define B 256
#define TE 300
#define TT 600
#define H 512
#define NIN 128
#define NPV 5
#define EMBD 32
#define NHE 16
#define WPJ 40704

__device__ float g_h0a[B * H], g_h0b[B * H];
__device__ float g_h1a[B * H], g_h1b[B * H];
__device__ float g_z[B * 256];
__device__ float g_embs[B * EMBD];
__device__ unsigned g_bar_count;
__device__ unsigned g_bar_sense;
__device__ uint4 g_wfrag[32 * WPJ];

__device__ __forceinline__ void gsync(unsigned& sense) {
    __syncthreads();
    if (threadIdx.x == 0) {
        __threadfence();
        unsigned prev = atomicAdd(&g_bar_count, 1u);
        if (prev == (unsigned)(NBLK - 1)) {
            atomicExch(&g_bar_count, 0u);
            __threadfence();
            *((volatile unsigned*)&g_bar_sense) = sense ^ 1u;
        } else {
            while (*((volatile unsigned*)&g_bar_sense) == sense) __nanosleep(32);
            __threadfence();
        }
    }
    sense ^= 1u;
    __syncthreads();
}

__device__ __forceinline__ void wgbar(int bid) {
    asm volatile("bar.sync %0, 256;" :: "r"(bid) : "memory");
}
__device__ __forceinline__ void cpa16(void* dst, const void* src) {
    unsigned ds = (unsigned)__cvta_generic_to_shared(dst);
    asm volatile("cp.async.ca.shared.global [%0],[%1],16;" :: "r"(ds), "l"(src));
}
__device__ __forceinline__ void cpcommit() { asm volatile("cp.async.commit_group;"); }
__device__ __forceinline__ void cpwait0() { asm volatile("cp.async.wait_group 0;"); }
__device__ __forceinline__ float sigf(float x) { return 1.f / (1.f + __expf(-x)); }
__device__ __forceinline__ void ldm4(unsigned* r, unsigned a) {
    asm volatile("ldmatrix.sync.aligned.m8n8.x4.shared.b16 {%0,%1,%2,%3},[%4];"
        : "=r"(r[0]), "=r"(r[1]), "=r"(r[2]), "=r"(r[3]) : "r"(a));
}
__device__ __forceinline__ void mmabf(float* d, const unsigned* a, const unsigned* b) {
    asm volatile("mma.sync.aligned.m16n8k16.row.col.f32.bf16.bf16.f32 "
        "{%0,%1,%2,%3},{%4,%5,%6,%7},{%8,%9},{%0,%1,%2,%3};"
        : "+f"(d[0]), "+f"(d[1]), "+f"(d[2]), "+f"(d[3])
        : "r"(a[0]), "r"(a[1]), "r"(a[2]), "r"(a[3]), "r"(b[0]), "r"(b[1]));
}
__device__ __forceinline__ unsigned pk2(float a, float b) {
    __nv_bfloat162 t = __floats2bfloat162_rn(a, b);
    return *(unsigned*)&t;
}
__device__ __forceinline__ float bflo(float x) {
    return x - __bfloat162float(__float2bfloat16(x));
}

// ---- 3-gate GEMM, 64m x 48n per 256-thread half; K window [ks0*16, (ks0+kcnt)*16) ----
template <int AMODE>
__device__ void gemm3(const float* __restrict__ A, int ldA,
                      const uint4* __restrict__ wf, int KsTot, int ks0, int kcnt,
                      int m0, __nv_bfloat16* sAh, __nv_bfloat16* sAl, uint4* sWf,
                      float* __restrict__ sG, int bid, int tl) {
    const int lane = tl & 31, warp = tl >> 5;
    const int wm = warp >> 1, wn = warp & 1;
    const int NC = kcnt >> 2;
    const int kbase = ks0 << 4;
    float4 ar[4];
    float d[3][4] = {{0,0,0,0},{0,0,0,0},{0,0,0,0}};

    auto ldgA = [&](int kb) {
#pragma unroll
        for (int i = 0; i < 4; i++) {
            int f = tl + (i << 8), m = f >> 4, kq = f & 15, kk = kbase + kb + (kq << 2);
            if (AMODE == 1) {
                if (kk < 128) ar[i] = *(const float4*)&A[(m0 + m) * ldA + kk];
                else if (kk < 160) ar[i] = *(const float4*)&g_embs[(m0 + m) * EMBD + (kk - 128)];
                else ar[i] = make_float4(0.f, 0.f, 0.f, 0.f);
            } else {
                ar[i] = *(const float4*)&A[(m0 + m) * ldA + kk];
            }
        }
    };
    auto stA = [&](int pb) {
        __nv_bfloat16 *ah = sAh + pb * 4608, *al = sAl + pb * 4608;
#pragma unroll
        for (int i = 0; i < 4; i++) {
            int f = tl + (i << 8), m = f >> 4, kq = f & 15, o = m * 72 + (kq << 2);
            *(uint2*)&ah[o] = make_uint2(pk2(ar[i].x, ar[i].y), pk2(ar[i].z, ar[i].w));
            *(uint2*)&al[o] = make_uint2(pk2(bflo(ar[i].x), bflo(ar[i].y)),
                                         pk2(bflo(ar[i].z), bflo(ar[i].w)));
        }
    };
    auto wcopy = [&](int c, int pb) {
        uint4* dst = sWf + pb * 768;
#pragma unroll
        for (int i = 0; i < 3; i++) {
            int f = tl + (i << 8);
            if (f < 768) {
                int q = f >> 7, r = f & 127;
                cpa16(dst + f, wf + (q * KsTot + ks0 + (c << 2)) * 32 + r);
            }
        }
        cpcommit();
    };

    const int arow = wm * 16 + (((lane >> 3) & 1) << 3) + (lane & 7);
    const int akoff = (lane >> 4) << 3;

    auto comp = [&](int pb) {
        const __nv_bfloat16 *ah = sAh + pb * 4608, *al = sAl + pb * 4608;
        const uint4* wb = sWf + pb * 768;
#pragma unroll
        for (int ks = 0; ks < 4; ks++) {
            unsigned Ah[4], Al[4];
            ldm4(Ah, (unsigned)__cvta_generic_to_shared(&ah[arow * 72 + (ks << 4) + akoff]));
            ldm4(Al, (unsigned)__cvta_generic_to_shared(&al[arow * 72 + (ks << 4) + akoff]));
#pragma unroll
            for (int nb = 0; nb < 3; nb++) {
                uint4 w = wb[(wn * 3 + nb) * 128 + (ks << 5) + lane];
                mmabf(d[nb], Ah, &w.x);
                mmabf(d[nb], Ah, &w.z);
                mmabf(d[nb], Al, &w.x);
            }
        }
    };

    ldgA(0); stA(0);
    if (NC > 1) ldgA(64);
    wcopy(0, 0);
    cpwait0();
    wgbar(bid);
    for (int c = 0; c < NC; c++) {
        if (c + 1 < NC) wcopy(c + 1, (c + 1) & 1);
        comp(c & 1);
        if (c + 1 < NC) {
            stA((c + 1) & 1);
            if (c + 2 < NC) ldgA((c + 2) << 6);
        }
        cpwait0();
        wgbar(bid);
    }
    int mrow = wm * 16 + (lane >> 2);
#pragma unroll
    for (int nb = 0; nb < 3; nb++) {
        int n = wn * 24 + nb * 8 + ((lane & 3) << 1);
        *(float2*)&sG[mrow * 52 + n] = make_float2(d[nb][0], d[nb][1]);
        *(float2*)&sG[(mrow + 8) * 52 + n] = make_float2(d[nb][2], d[nb][3]);
    }
}

// enc L0 combine: gi = sGi; gh = sGhA + sGhB (K-split partials)
__device__ __forceinline__ void combineE0(const float* sGi, const float* sGhA, const float* sGhB,
        const float* bias, const float* __restrict__ hin, float* __restrict__ hout,
        int m0, int j0, int tid) {
    int tm = tid >> 4, tn = tid & 15, j = j0 + tn;
    float bi0 = bias[tn], bi1 = bias[16 + tn], bi2 = bias[32 + tn];
    float bh0 = bias[48 + tn], bh1 = bias[64 + tn], bh2 = bias[80 + tn];
#pragma unroll
    for (int r = 0; r < 2; r++) {
        int ml = tm * 2 + r, b = m0 + ml;
        float ir = sGi[ml * 52 + tn] + bi0;
        float iz = sGi[ml * 52 + 16 + tn] + bi1;
        float in_ = sGi[ml * 52 + 32 + tn] + bi2;
        float hr = sGhA[ml * 52 + tn] + sGhB[ml * 52 + tn] + bh0;
        float hz = sGhA[ml * 52 + 16 + tn] + sGhB[ml * 52 + 16 + tn] + bh1;
        float hn = sGhA[ml * 52 + 32 + tn] + sGhB[ml * 52 + 32 + tn] + bh2;
        float rr = sigf(ir + hr), zz = sigf(iz + hz), nn = tanhf(in_ + rr * hn);
        hout[b * H + j] = (1.f - zz) * nn + zz * hin[b * H + j];
    }
}

// dec L0 combine: gi = sGi (+ rank-5 pv correction); gh = sGh
template <bool PVLOC>
__device__ __forceinline__ void combineD0(const float* sGi, const float* sGh,
        const float* bias, const float* pvw, const float* pvsrc,
        const float* __restrict__ hin, float* __restrict__ hout, int m0, int j0, int tid) {
    int tm = tid >> 4, tn = tid & 15, j = j0 + tn;
    float bi0 = bias[tn], bi1 = bias[16 + tn], bi2 = bias[32 + tn];
    float bh0 = bias[48 + tn], bh1 = bias[64 + tn], bh2 = bias[80 + tn];
#pragma unroll
    for (int r = 0; r < 2; r++) {
        int ml = tm * 2 + r, b = m0 + ml;
        float ir = sGi[ml * 52 + tn] + bi0;
        float iz = sGi[ml * 52 + 16 + tn] + bi1;
        float in_ = sGi[ml * 52 + 32 + tn] + bi2;
        const float* pv = PVLOC ? (pvsrc + ml * 5) : (pvsrc + b * 5);
#pragma unroll
        for (int q = 0; q < 5; q++) {
            float pq = pv[q];
            ir += pq * pvw[tn * 5 + q];
            iz += pq * pvw[80 + tn * 5 + q];
            in_ += pq * pvw[160 + tn * 5 + q];
        }
        float hr = sGh[ml * 52 + tn] + bh0;
        float hz = sGh[ml * 52 + 16 + tn] + bh1;
        float hn = sGh[ml * 52 + 32 + tn] + bh2;
        float rr = sigf(ir + hr), zz = sigf(iz + hz), nn = tanhf(in_ + rr * hn);
        hout[b * H + j] = (1.f - zz) * nn + zz * hin[b * H + j];
    }
}

// L1 combine: gi = sGi, gh = sGh
__device__ __forceinline__ void combine3(const float* sGi, const float* sGh, const float* bias,
        const float* __restrict__ hin, float* __restrict__ hout, int m0, int j0, int tid) {
    int tm = tid >> 4, tn = tid & 15, j = j0 + tn;
    float bi0 = bias[tn], bi1 = bias[16 + tn], bi2 = bias[32 + tn];
    float bh0 = bias[48 + tn], bh1 = bias[64 + tn], bh2 = bias[80 + tn];
#pragma unroll
    for (int r = 0; r < 2; r++) {
        int ml = tm * 2 + r, b = m0 + ml;
        float ir = sGi[ml * 52 + tn] + bi0;
        float iz = sGi[ml * 52 + 16 + tn] + bi1;
        float in_ = sGi[ml * 52 + 32 + tn] + bi2;
        float hr = sGh[ml * 52 + tn] + bh0;
        float hz = sGh[ml * 52 + 16 + tn] + bh1;
        float hn = sGh[ml * 52 + 32 + tn] + bh2;
        float rr = sigf(ir + hr), zz = sigf(iz + hz), nn = tanhf(in_ + rr * hn);
        hout[b * H + j] = (1.f - zz) * nn + zz * hin[b * H + j];
    }
}

// heads1 on half1 (256 threads), named barrier 2
__device__ void heads1h(float* As2, float* Ws2, const float* __restrict__ d2,
                        const float* __restrict__ fc1W, const float* __restrict__ fc1b,
                        const float* __restrict__ he1W, const float* __restrict__ he1b, int tl) {
    int m0 = (blockIdx.x >> 3) * 16, n0 = (blockIdx.x & 7) * 32;
    int m = tl & 15, n2 = (tl >> 4) * 2;
    float acc0 = 0.f, acc1 = 0.f;
    for (int kb = 0; kb < H; kb += 32) {
#pragma unroll
        for (int i = 0; i < 2; i++) {
            int f = tl + (i << 8), kk = f & 31, mm = f >> 5;
            As2[kk * 17 + mm] = d2[(m0 + mm) * H + kb + kk];
        }
#pragma unroll
        for (int i = 0; i < 4; i++) {
            int f = tl + (i << 8), kk = f & 31, nn = f >> 5;
            int ng = n0 + nn;
            const float* Wr = (ng < 128) ? (fc1W + ng * H) : (he1W + (ng - 128) * H);
            Ws2[kk * 34 + nn] = Wr[kb + kk];
        }
        wgbar(2);
#pragma unroll
        for (int k = 0; k < 32; k++) {
            float a = As2[k * 17 + m];
            float2 w = *(const float2*)&Ws2[k * 34 + n2];
            acc0 += a * w.x; acc1 += a * w.y;
        }
        wgbar(2);
    }
    int b = m0 + m, ng0 = n0 + n2;
    float b0 = (ng0 < 128) ? fc1b[ng0] : he1b[ng0 - 128];
    float b1 = (ng0 + 1 < 128) ? fc1b[ng0 + 1] : he1b[ng0 + 1 - 128];
    g_z[b * 256 + ng0] = fmaxf(acc0 + b0, 0.f);
    g_z[b * 256 + ng0 + 1] = fmaxf(acc1 + b1, 0.f);
}

// local pv(t) for this CTA's 64 m-rows, from g_z and cached fc2
__device__ void pvcalc(float* sPvloc, const float* sPv2W, const float* sPv2b, int m0, int tid) {
    int w = tid >> 5, lane = tid & 31;
#pragma unroll
    for (int rr = 0; rr < 4; rr++) {
        int bl = w * 4 + rr, b = m0 + bl;
        float z0 = g_z[b * 256 + lane], z1 = g_z[b * 256 + 32 + lane];
        float z2 = g_z[b * 256 + 64 + lane], z3 = g_z[b * 256 + 96 + lane];
#pragma unroll
        for (int q = 0; q < 5; q++) {
            float s = z0 * sPv2W[q * 128 + lane] + z1 * sPv2W[q * 128 + 32 + lane]
                    + z2 * sPv2W[q * 128 + 64 + lane] + z3 * sPv2W[q * 128 + 96 + lane];
#pragma unroll
            for (int off = 16; off; off >>= 1) s += __shfl_xor_sync(0xffffffffu, s, off);
            if (lane == 0) sPvloc[bl * 5 + q] = s + sPv2b[q];
        }
    }
}

__device__ void heads2(float* zs, int t,
                       const float* __restrict__ fc2W, const float* __restrict__ fc2b,
                       const float* __restrict__ he2W, const float* __restrict__ he2b,
                       float* __restrict__ out) {
    int tid = threadIdx.x, b0 = blockIdx.x * 2;
    zs[tid] = g_z[b0 * 256 + tid];
    __syncthreads();
    int warp = tid >> 5, lane = tid & 31;
    for (int dd = warp; dd < 42; dd += 16) {
        int bb = dd / 21, o = dd % 21;
        const float* wrow; int kbase; float bias;
        if (o < 5) { wrow = fc2W + o * 128; kbase = 0; bias = fc2b[o]; }
        else       { wrow = he2W + (o - 5) * 128; kbase = 128; bias = he2b[o - 5]; }
        float s = 0.f;
#pragma unroll
        for (int kk = 0; kk < 128; kk += 32)
            s += zs[bb * 256 + kbase + kk + lane] * wrow[kk + lane];
#pragma unroll
        for (int off = 16; off; off >>= 1) s += __shfl_xor_sync(0xffffffffu, s, off);
        if (lane == 0) {
            float v = s + bias; int b = b0 + bb;
            if (o < 5) out[b * (TT * NPV) + t * NPV + o] = v;
            else out[B * TT * NPV + b * (TT * NHE) + t * NHE + (o - 5)] = v;
        }
    }
    __syncthreads();
}

struct P {
    const float *x_cv, *x_cv_target, *pv_init;
    const int* scenario;
    const float* emb;
    const float *eW0i, *eW0h, *eb0i, *eb0h, *eW1i, *eW1h, *eb1i, *eb1h;
    const float *dW0i, *dW0h, *db0i, *db0h, *dW1i, *dW1h, *db1i, *db1h;
    const float *fc1W, *fc1b, *fc2W, *fc2b, *he1W, *he1b, *he2W, *he2b;
    float* out;
};

#define SMEM_BYTES 177792

__global__ void __launch_bounds__(NTHR, 1) gru_kernel(P p) {
    extern __shared__ __align__(16) char sm[];
    __nv_bfloat16* sA0h = (__nv_bfloat16*)sm;      // 2*4608 bf16 each
    __nv_bfloat16* sA0l = sA0h + 9216;
    __nv_bfloat16* sA1h = sA0l + 9216;
    __nv_bfloat16* sA1l = sA1h + 9216;
    uint4* sW0 = (uint4*)(sA1l + 9216);            // 2*768 uint4 each
    uint4* sW1 = sW0 + 1536;
    float* sGi  = (float*)(sW1 + 1536);            // 64*52 each
    float* sGh  = sGi + 3328;
    float* sGh2 = sGh + 3328;
    float* sBias = sGh2 + 3328;                    // 384
    float* sPvw  = sBias + 384;                    // 240
    float* sPv2W = sPvw + 240;                     // 640
    float* sPv2b = sPv2W + 640;                    // 8
    float* sPvloc = sPv2b + 8;                     // 320
    float* sH = sPvloc + 320;                      // 544 + 1088 + 512

    unsigned sense = *((volatile unsigned*)&g_bar_sense);
    int tid = threadIdx.x;
    int half = tid >> 8, tl = tid & 255;
    int mt = blockIdx.x >> 5, jt = blockIdx.x & 31;
    int m0 = mt << 6, j0 = jt << 4;
    int gt = blockIdx.x * NTHR + tid;

    for (int i = gt; i < B * H; i += NBLK * NTHR) { g_h0a[i] = 0.f; g_h1a[i] = 0.f; }
    for (int i = gt; i < B * EMBD; i += NBLK * NTHR)
        g_embs[i] = p.emb[p.scenario[i >> 5] * EMBD + (i & 31)];
    {
        const float* bI[4] = { p.eb0i, p.eb1i, p.db0i, p.db1i };
        const float* bH[4] = { p.eb0h, p.eb1h, p.db0h, p.db1h };
        for (int idx = tid; idx < 384; idx += NTHR) {
            int ph = idx / 96, r = idx % 96, g = r >> 4, jj = r & 15;
            sBias[idx] = (g < 3) ? bI[ph][(g << 9) + j0 + jj] : bH[ph][((g - 3) << 9) + j0 + jj];
        }
        for (int idx = tid; idx < 240; idx += NTHR) {
            int g = idx / 80, r = idx % 80, jj = r / 5, q = r % 5;
            sPvw[idx] = p.dW0i[((g << 9) + j0 + jj) * 133 + 128 + q];
        }
        for (int idx = tid; idx < 640; idx += NTHR) sPv2W[idx] = p.fc2W[idx];
        if (tid < 5) sPv2b[tid] = p.fc2b[tid];
    }
    if (mt == 0) {   // one-time W fragment preconversion (32 CTAs cover all jt)
        const float* WP[8] = { p.eW0i, p.eW0h, p.eW1i, p.eW1h, p.dW0i, p.dW0h, p.dW1i, p.dW1h };
        const int LDW[8] = { 160, 512, 512, 512, 133, 512, 512, 512 };
        const int KS[8]  = { 12, 32, 32, 32, 8, 32, 32, 32 };
        const int KV[8]  = { 160, 512, 512, 512, 133, 512, 512, 512 };
        const int OFFm[8] = { 0, 2304, 8448, 14592, 20736, 22272, 28416, 34560 };
        uint4* base = g_wfrag + jt * WPJ;
        for (int m = 0; m < 8; m++) {
            const float* W = WP[m]; int ldw = LDW[m], Ks = KS[m], kv = KV[m];
            int tot = 6 * Ks * 32;
            for (int f = tid; f < tot; f += NTHR) {
                int lane = f & 31, rest = f >> 5;
                int ks = rest % Ks, nbg = rest / Ks;
                int nt = nbg * 8 + (lane >> 2);
                int grow = (nt >> 4) * 512 + jt * 16 + (nt & 15);
                int k0 = ks * 16 + ((lane & 3) << 1);
                const float* r = W + grow * ldw;
                float e0 = (k0 < kv) ? r[k0] : 0.f;
                float e1 = (k0 + 1 < kv) ? r[k0 + 1] : 0.f;
                float e8 = (k0 + 8 < kv) ? r[k0 + 8] : 0.f;
                float e9 = (k0 + 9 < kv) ? r[k0 + 9] : 0.f;
                base[OFFm[m] + (nbg * Ks + ks) * 32 + lane] =
                    make_uint4(pk2(e0, e1), pk2(e8, e9),
                               pk2(bflo(e0), bflo(e1)), pk2(bflo(e8), bflo(e9)));
            }
        }
    }
    gsync(sense);

    const uint4* WB = g_wfrag + jt * WPJ;
    float* h0buf[2] = { g_h0a, g_h0b };
    float* h1buf[2] = { g_h1a, g_h1b };

    // ---------------- encoder ----------------
    for (int t = 0; t < TE; t++) {
        int rd = t & 1, wr = rd ^ 1;
        // phase1 balanced: half0: gi(K192) + gh[0:128); half1: gh[128:512)
        if (!half) {
            gemm3<1>(p.x_cv + t * NIN, TE * NIN, WB + 0, 12, 0, 12, m0, sA0h, sA0l, sW0, sGi, 1, tl);
            gemm3<0>(h0buf[rd], H, WB + 2304, 32, 0, 8, m0, sA0h, sA0l, sW0, sGh2, 1, tl);
        } else {
            gemm3<0>(h0buf[rd], H, WB + 2304, 32, 8, 24, m0, sA1h, sA1l, sW1, sGh, 2, tl);
        }
        __syncthreads();
        combineE0(sGi, sGh2, sGh, sBias, h0buf[rd], h0buf[wr], m0, j0, tid);
        gsync(sense);
        if (!half) gemm3<0>(h0buf[wr], H, WB + 8448, 32, 0, 32, m0, sA0h, sA0l, sW0, sGi, 1, tl);
        else       gemm3<0>(h1buf[rd], H, WB + 14592, 32, 0, 32, m0, sA1h, sA1l, sW1, sGh, 2, tl);
        __syncthreads();
        combine3(sGi, sGh, sBias + 96, h1buf[rd], h1buf[wr], m0, j0, tid);
        __syncthreads();
    }

    // ---------------- decoder ----------------
    // P0: h0(next) from gi0(0) + gh0(enc-final h0) + pv_init
    if (!half) gemm3<0>(p.x_cv_target, TT * NIN, WB + 20736, 8, 0, 8, m0, sA0h, sA0l, sW0, sGi, 1, tl);
    else       gemm3<0>(h0buf[0], H, WB + 22272, 32, 0, 32, m0, sA1h, sA1l, sW1, sGh, 2, tl);
    __syncthreads();
    combineD0<false>(sGi, sGh, sBias + 192, sPvw, p.pv_init, h0buf[0], h0buf[1], m0, j0, tid);
    gsync(sense);

    for (int t = 0; t < TT; t++) {
        float* h0cur = h0buf[(t + 1) & 1];
        // D1: gi1 || gh1, then C1
        if (!half) gemm3<0>(h0cur, H, WB + 28416, 32, 0, 32, m0, sA0h, sA0l, sW0, sGi, 1, tl);
        else       gemm3<0>(h1buf[t & 1], H, WB + 34560, 32, 0, 32, m0, sA1h, sA1l, sW1, sGh, 2, tl);
        __syncthreads();
        combine3(sGi, sGh, sBias + 288, h1buf[t & 1], h1buf[(t + 1) & 1], m0, j0, tid);
        gsync(sense);
        // D2: half0: gh0(t+1) + gi0(t+1); half1: heads1(t)
        if (!half) {
            if (t + 1 < TT) {
                gemm3<0>(h0cur, H, WB + 22272, 32, 0, 32, m0, sA0h, sA0l, sW0, sGh2, 1, tl);
                gemm3<0>(p.x_cv_target + (t + 1) * NIN, TT * NIN, WB + 20736, 8, 0, 8, m0, sA0h, sA0l, sW0, sGi, 1, tl);
            }
        } else {
            heads1h(sH, sH + 544, h1buf[(t + 1) & 1], p.fc1W, p.fc1b, p.he1W, p.he1b, tl);
        }
        gsync(sense);
        // D3: pv local + heads2 + C0(t+1)
        pvcalc(sPvloc, sPv2W, sPv2b, m0, tid);
        __syncthreads();
        heads2(sH + 544 + 1088, t, p.fc2W, p.fc2b, p.he2W, p.he2b, p.out);
        if (t + 1 < TT)
            combineD0<true>(sGi, sGh2, sBias + 192, sPvw, sPvloc, h0cur, h0buf[t & 1], m0, j0, tid);
        gsync(sense);
    }
}

extern "C" void kernel_launch(void* const* d_in, const int* in_sizes, int n_in,
                              void* d_out, int out_size) {
    (void)in_sizes; (void)n_in; (void)out_size;
    cudaFuncSetAttribute(gru_kernel, cudaFuncAttributeMaxDynamicSharedMemorySize, SMEM_BYTES);
    P p;
    p.x_cv        = (const float*)d_in[0];
    p.x_cv_target = (const float*)d_in[1];
    p.pv_init     = (const float*)d_in[2];
    p.scenario    = (const int*)d_in[3];
    p.emb         = (const float*)d_in[4];
    p.eW0i = (const float*)d_in[5];  p.eW0h = (const float*)d_in[6];
    p.eb0i = (const float*)d_in[7];  p.eb0h = (const float*)d_in[8];
    p.eW1i = (const float*)d_in[9];  p.eW1h = (const float*)d_in[10];
    p.eb1i = (const float*)d_in[11]; p.eb1h = (const float*)d_in[12];
    p.dW0i = (const float*)d_in[13]; p.dW0h = (const float*)d_in[14];
    p.db0i = (const float*)d_in[15]; p.db0h = (const float*)d_in[16];
    p.dW1i = (const float*)d_in[17]; p.dW1h = (const float*)d_in[18];
    p.db1i = (const float*)d_in[19]; p.db1h = (const float*)d_in[20];
    p.fc1W = (const float*)d_in[21]; p.fc1b = (const float*)d_in[22];
    p.fc2W = (const float*)d_in[23]; p.fc2b = (const float*)d_in[24];
    p.he1W = (const float*)d_in[25]; p.he1b = (const float*)d_in[26];
    p.he2W = (const float*)d_in[27]; p.he2b = (const float*)d_in[28];
    p.out  = (float*)d_out;
    gru_kernel<<<NBLK, NTHR, SMEM_BYTES>>>(p);
}

// round 15
// speedup vs baseline: 1.0521x; 1.0521x over previous
#include <cuda_runtime.h>
#include <cuda_bf16.h>

#define NBLK 128
#define NTHR 512
#define B 256
#define TE 300
#define TT 600
#define H 512
#define NIN 128
#define NPV 5
#define EMBD 32
#define NHE 16
#define WPJ 40704

__device__ float g_h0a[B * H], g_h0b[B * H];
__device__ float g_h1a[B * H], g_h1b[B * H];
__device__ __align__(16) __nv_bfloat16 g_h0h[2][B * H], g_h0l[2][B * H];
__device__ __align__(16) __nv_bfloat16 g_h1h[2][B * H], g_h1l[2][B * H];
__device__ __align__(16) __nv_bfloat16 g_exh[(size_t)TE * B * 192], g_exl[(size_t)TE * B * 192];
__device__ __align__(16) __nv_bfloat16 g_dxh[(size_t)TT * B * 128], g_dxl[(size_t)TT * B * 128];
__device__ float g_z[B * 256];
__device__ float g_embs[B * EMBD];
__device__ unsigned g_bar_count;
__device__ unsigned g_bar_sense;
__device__ uint4 g_wfrag[32 * WPJ];

__device__ __forceinline__ void gsync(unsigned& sense) {
    __syncthreads();
    if (threadIdx.x == 0) {
        __threadfence();
        unsigned prev = atomicAdd(&g_bar_count, 1u);
        if (prev == (unsigned)(NBLK - 1)) {
            atomicExch(&g_bar_count, 0u);
            __threadfence();
            *((volatile unsigned*)&g_bar_sense) = sense ^ 1u;
        } else {
            while (*((volatile unsigned*)&g_bar_sense) == sense) __nanosleep(32);
            __threadfence();
        }
    }
    sense ^= 1u;
    __syncthreads();
}

__device__ __forceinline__ void wgbar(int bid) {
    asm volatile("bar.sync %0, 256;" :: "r"(bid) : "memory");
}
__device__ __forceinline__ void cpa16(void* dst, const void* src) {
    unsigned ds = (unsigned)__cvta_generic_to_shared(dst);
    asm volatile("cp.async.ca.shared.global [%0],[%1],16;" :: "r"(ds), "l"(src));
}
__device__ __forceinline__ void cpcommit() { asm volatile("cp.async.commit_group;"); }
__device__ __forceinline__ void cpwait0() { asm volatile("cp.async.wait_group 0;"); }
__device__ __forceinline__ float sigf(float x) { return 1.f / (1.f + __expf(-x)); }
__device__ __forceinline__ void ldm4(unsigned* r, unsigned a) {
    asm volatile("ldmatrix.sync.aligned.m8n8.x4.shared.b16 {%0,%1,%2,%3},[%4];"
        : "=r"(r[0]), "=r"(r[1]), "=r"(r[2]), "=r"(r[3]) : "r"(a));
}
__device__ __forceinline__ void mmabf(float* d, const unsigned* a, const unsigned* b) {
    asm volatile("mma.sync.aligned.m16n8k16.row.col.f32.bf16.bf16.f32 "
        "{%0,%1,%2,%3},{%4,%5,%6,%7},{%8,%9},{%0,%1,%2,%3};"
        : "+f"(d[0]), "+f"(d[1]), "+f"(d[2]), "+f"(d[3])
        : "r"(a[0]), "r"(a[1]), "r"(a[2]), "r"(a[3]), "r"(b[0]), "r"(b[1]));
}
__device__ __forceinline__ unsigned pk2(float a, float b) {
    __nv_bfloat162 t = __floats2bfloat162_rn(a, b);
    return *(unsigned*)&t;
}
__device__ __forceinline__ float bflo(float x) {
    return x - __bfloat162float(__float2bfloat16(x));
}

// ---- 3-gate GEMM, 64m x 48n per 256-thread half. A = pre-split bf16 hi/lo in global,
// fetched by cp.async straight into ldmatrix layout. W = preconverted fragment file. ----
__device__ void gemm3(const __nv_bfloat16* __restrict__ Ah, const __nv_bfloat16* __restrict__ Al,
                      int ldA, const uint4* __restrict__ wf, int KsTot, int ks0, int kcnt,
                      int m0, __nv_bfloat16* sAh, __nv_bfloat16* sAl, uint4* sWf,
                      float* __restrict__ sG, int bid, int tl) {
    const int lane = tl & 31, warp = tl >> 5;
    const int wm = warp >> 1, wn = warp & 1;
    const int NC = kcnt >> 2;
    const int kbase = ks0 << 4;
    float d[3][4] = {{0,0,0,0},{0,0,0,0},{0,0,0,0}};

    auto issue = [&](int c, int pb) {
        __nv_bfloat16* dh = sAh + pb * 4608;
        __nv_bfloat16* dl = sAl + pb * 4608;
#pragma unroll
        for (int i = 0; i < 2; i++) {
            int f = tl + (i << 8), m = f >> 3, kq = f & 7;
            size_t go = (size_t)(m0 + m) * ldA + kbase + (c << 6) + (kq << 3);
            int so = m * 72 + (kq << 3);
            cpa16(dh + so, Ah + go);
            cpa16(dl + so, Al + go);
        }
        uint4* dw = sWf + pb * 768;
#pragma unroll
        for (int i = 0; i < 3; i++) {
            int f = tl + (i << 8);
            if (f < 768) {
                int q = f >> 7, r = f & 127;
                cpa16(dw + f, wf + (q * KsTot + ks0 + (c << 2)) * 32 + r);
            }
        }
        cpcommit();
    };

    const int arow = wm * 16 + (((lane >> 3) & 1) << 3) + (lane & 7);
    const int akoff = (lane >> 4) << 3;

    auto comp = [&](int pb) {
        const __nv_bfloat16 *ah = sAh + pb * 4608, *al = sAl + pb * 4608;
        const uint4* wb = sWf + pb * 768;
#pragma unroll
        for (int ks = 0; ks < 4; ks++) {
            unsigned Ahh[4], All[4];
            ldm4(Ahh, (unsigned)__cvta_generic_to_shared(&ah[arow * 72 + (ks << 4) + akoff]));
            ldm4(All, (unsigned)__cvta_generic_to_shared(&al[arow * 72 + (ks << 4) + akoff]));
#pragma unroll
            for (int nb = 0; nb < 3; nb++) {
                uint4 w = wb[(wn * 3 + nb) * 128 + (ks << 5) + lane];
                mmabf(d[nb], Ahh, &w.x);
                mmabf(d[nb], Ahh, &w.z);
                mmabf(d[nb], All, &w.x);
            }
        }
    };

    issue(0, 0);
    cpwait0();
    wgbar(bid);
    for (int c = 0; c < NC; c++) {
        if (c + 1 < NC) issue(c + 1, (c + 1) & 1);
        comp(c & 1);
        cpwait0();
        wgbar(bid);
    }
    int mrow = wm * 16 + (lane >> 2);
#pragma unroll
    for (int nb = 0; nb < 3; nb++) {
        int n = wn * 24 + nb * 8 + ((lane & 3) << 1);
        *(float2*)&sG[mrow * 52 + n] = make_float2(d[nb][0], d[nb][1]);
        *(float2*)&sG[(mrow + 8) * 52 + n] = make_float2(d[nb][2], d[nb][3]);
    }
}

__device__ __forceinline__ void sthl(float hv, int idx, float* hout,
                                     __nv_bfloat16* hh, __nv_bfloat16* hl) {
    hout[idx] = hv;
    __nv_bfloat16 h = __float2bfloat16(hv);
    hh[idx] = h;
    hl[idx] = __float2bfloat16(hv - __bfloat162float(h));
}

// enc L0 combine: gh = sGhA + sGhB (K-split partials)
__device__ __forceinline__ void combineE0(const float* sGi, const float* sGhA, const float* sGhB,
        const float* bias, const float* __restrict__ hin, float* hout,
        __nv_bfloat16* hh, __nv_bfloat16* hl, int m0, int j0, int tid) {
    int tm = tid >> 4, tn = tid & 15, j = j0 + tn;
    float bi0 = bias[tn], bi1 = bias[16 + tn], bi2 = bias[32 + tn];
    float bh0 = bias[48 + tn], bh1 = bias[64 + tn], bh2 = bias[80 + tn];
#pragma unroll
    for (int r = 0; r < 2; r++) {
        int ml = tm * 2 + r, b = m0 + ml;
        float ir = sGi[ml * 52 + tn] + bi0;
        float iz = sGi[ml * 52 + 16 + tn] + bi1;
        float in_ = sGi[ml * 52 + 32 + tn] + bi2;
        float hr = sGhA[ml * 52 + tn] + sGhB[ml * 52 + tn] + bh0;
        float hz = sGhA[ml * 52 + 16 + tn] + sGhB[ml * 52 + 16 + tn] + bh1;
        float hn = sGhA[ml * 52 + 32 + tn] + sGhB[ml * 52 + 32 + tn] + bh2;
        float rr = sigf(ir + hr), zz = sigf(iz + hz), nn = tanhf(in_ + rr * hn);
        sthl((1.f - zz) * nn + zz * hin[b * H + j], b * H + j, hout, hh, hl);
    }
}

template <bool PVLOC>
__device__ __forceinline__ void combineD0(const float* sGi, const float* sGh,
        const float* bias, const float* pvw, const float* pvsrc,
        const float* __restrict__ hin, float* hout,
        __nv_bfloat16* hh, __nv_bfloat16* hl, int m0, int j0, int tid) {
    int tm = tid >> 4, tn = tid & 15, j = j0 + tn;
    float bi0 = bias[tn], bi1 = bias[16 + tn], bi2 = bias[32 + tn];
    float bh0 = bias[48 + tn], bh1 = bias[64 + tn], bh2 = bias[80 + tn];
#pragma unroll
    for (int r = 0; r < 2; r++) {
        int ml = tm * 2 + r, b = m0 + ml;
        float ir = sGi[ml * 52 + tn] + bi0;
        float iz = sGi[ml * 52 + 16 + tn] + bi1;
        float in_ = sGi[ml * 52 + 32 + tn] + bi2;
        const float* pv = PVLOC ? (pvsrc + ml * 5) : (pvsrc + b * 5);
#pragma unroll
        for (int q = 0; q < 5; q++) {
            float pq = pv[q];
            ir += pq * pvw[tn * 5 + q];
            iz += pq * pvw[80 + tn * 5 + q];
            in_ += pq * pvw[160 + tn * 5 + q];
        }
        float hr = sGh[ml * 52 + tn] + bh0;
        float hz = sGh[ml * 52 + 16 + tn] + bh1;
        float hn = sGh[ml * 52 + 32 + tn] + bh2;
        float rr = sigf(ir + hr), zz = sigf(iz + hz), nn = tanhf(in_ + rr * hn);
        sthl((1.f - zz) * nn + zz * hin[b * H + j], b * H + j, hout, hh, hl);
    }
}

__device__ __forceinline__ void combine3(const float* sGi, const float* sGh, const float* bias,
        const float* __restrict__ hin, float* hout,
        __nv_bfloat16* hh, __nv_bfloat16* hl, int m0, int j0, int tid) {
    int tm = tid >> 4, tn = tid & 15, j = j0 + tn;
    float bi0 = bias[tn], bi1 = bias[16 + tn], bi2 = bias[32 + tn];
    float bh0 = bias[48 + tn], bh1 = bias[64 + tn], bh2 = bias[80 + tn];
#pragma unroll
    for (int r = 0; r < 2; r++) {
        int ml = tm * 2 + r, b = m0 + ml;
        float ir = sGi[ml * 52 + tn] + bi0;
        float iz = sGi[ml * 52 + 16 + tn] + bi1;
        float in_ = sGi[ml * 52 + 32 + tn] + bi2;
        float hr = sGh[ml * 52 + tn] + bh0;
        float hz = sGh[ml * 52 + 16 + tn] + bh1;
        float hn = sGh[ml * 52 + 32 + tn] + bh2;
        float rr = sigf(ir + hr), zz = sigf(iz + hz), nn = tanhf(in_ + rr * hn);
        sthl((1.f - zz) * nn + zz * hin[b * H + j], b * H + j, hout, hh, hl);
    }
}

// heads1 on half1 (256 threads), named barrier 2
__device__ void heads1h(float* As2, float* Ws2, const float* __restrict__ d2,
                        const float* __restrict__ fc1W, const float* __restrict__ fc1b,
                        const float* __restrict__ he1W, const float* __restrict__ he1b, int tl) {
    int m0 = (blockIdx.x >> 3) * 16, n0 = (blockIdx.x & 7) * 32;
    int m = tl & 15, n2 = (tl >> 4) * 2;
    float acc0 = 0.f, acc1 = 0.f;
    for (int kb = 0; kb < H; kb += 32) {
#pragma unroll
        for (int i = 0; i < 2; i++) {
            int f = tl + (i << 8), kk = f & 31, mm = f >> 5;
            As2[kk * 17 + mm] = d2[(m0 + mm) * H + kb + kk];
        }
#pragma unroll
        for (int i = 0; i < 4; i++) {
            int f = tl + (i << 8), kk = f & 31, nn = f >> 5;
            int ng = n0 + nn;
            const float* Wr = (ng < 128) ? (fc1W + ng * H) : (he1W + (ng - 128) * H);
            Ws2[kk * 34 + nn] = Wr[kb + kk];
        }
        wgbar(2);
#pragma unroll
        for (int k = 0; k < 32; k++) {
            float a = As2[k * 17 + m];
            float2 w = *(const float2*)&Ws2[k * 34 + n2];
            acc0 += a * w.x; acc1 += a * w.y;
        }
        wgbar(2);
    }
    int b = m0 + m, ng0 = n0 + n2;
    float b0 = (ng0 < 128) ? fc1b[ng0] : he1b[ng0 - 128];
    float b1 = (ng0 + 1 < 128) ? fc1b[ng0 + 1] : he1b[ng0 + 1 - 128];
    g_z[b * 256 + ng0] = fmaxf(acc0 + b0, 0.f);
    g_z[b * 256 + ng0 + 1] = fmaxf(acc1 + b1, 0.f);
}

__device__ void pvcalc(float* sPvloc, const float* sPv2W, const float* sPv2b, int m0, int tid) {
    int w = tid >> 5, lane = tid & 31;
#pragma unroll
    for (int rr = 0; rr < 4; rr++) {
        int bl = w * 4 + rr, b = m0 + bl;
        float z0 = g_z[b * 256 + lane], z1 = g_z[b * 256 + 32 + lane];
        float z2 = g_z[b * 256 + 64 + lane], z3 = g_z[b * 256 + 96 + lane];
#pragma unroll
        for (int q = 0; q < 5; q++) {
            float s = z0 * sPv2W[q * 128 + lane] + z1 * sPv2W[q * 128 + 32 + lane]
                    + z2 * sPv2W[q * 128 + 64 + lane] + z3 * sPv2W[q * 128 + 96 + lane];
#pragma unroll
            for (int off = 16; off; off >>= 1) s += __shfl_xor_sync(0xffffffffu, s, off);
            if (lane == 0) sPvloc[bl * 5 + q] = s + sPv2b[q];
        }
    }
}

__device__ void heads2(float* zs, int t,
                       const float* __restrict__ fc2W, const float* __restrict__ fc2b,
                       const float* __restrict__ he2W, const float* __restrict__ he2b,
                       float* __restrict__ out) {
    int tid = threadIdx.x, b0 = blockIdx.x * 2;
    zs[tid] = g_z[b0 * 256 + tid];
    __syncthreads();
    int warp = tid >> 5, lane = tid & 31;
    for (int dd = warp; dd < 42; dd += 16) {
        int bb = dd / 21, o = dd % 21;
        const float* wrow; int kbase; float bias;
        if (o < 5) { wrow = fc2W + o * 128; kbase = 0; bias = fc2b[o]; }
        else       { wrow = he2W + (o - 5) * 128; kbase = 128; bias = he2b[o - 5]; }
        float s = 0.f;
#pragma unroll
        for (int kk = 0; kk < 128; kk += 32)
            s += zs[bb * 256 + kbase + kk + lane] * wrow[kk + lane];
#pragma unroll
        for (int off = 16; off; off >>= 1) s += __shfl_xor_sync(0xffffffffu, s, off);
        if (lane == 0) {
            float v = s + bias; int b = b0 + bb;
            if (o < 5) out[b * (TT * NPV) + t * NPV + o] = v;
            else out[B * TT * NPV + b * (TT * NHE) + t * NHE + (o - 5)] = v;
        }
    }
    __syncthreads();
}

struct P {
    const float *x_cv, *x_cv_target, *pv_init;
    const int* scenario;
    const float* emb;
    const float *eW0i, *eW0h, *eb0i, *eb0h, *eW1i, *eW1h, *eb1i, *eb1h;
    const float *dW0i, *dW0h, *db0i, *db0h, *dW1i, *dW1h, *db1i, *db1h;
    const float *fc1W, *fc1b, *fc2W, *fc2b, *he1W, *he1b, *he2W, *he2b;
    float* out;
};

#define SMEM_BYTES 177792

__global__ void __launch_bounds__(NTHR, 1) gru_kernel(P p) {
    extern __shared__ __align__(16) char sm[];
    __nv_bfloat16* sA0h = (__nv_bfloat16*)sm;      // 2*4608 bf16 each
    __nv_bfloat16* sA0l = sA0h + 9216;
    __nv_bfloat16* sA1h = sA0l + 9216;
    __nv_bfloat16* sA1l = sA1h + 9216;
    uint4* sW0 = (uint4*)(sA1l + 9216);            // 2*768 uint4 each
    uint4* sW1 = sW0 + 1536;
    float* sGi  = (float*)(sW1 + 1536);            // 64*52 each
    float* sGh  = sGi + 3328;
    float* sGh2 = sGh + 3328;
    float* sBias = sGh2 + 3328;                    // 384
    float* sPvw  = sBias + 384;                    // 240
    float* sPv2W = sPvw + 240;                     // 640
    float* sPv2b = sPv2W + 640;                    // 8
    float* sPvloc = sPv2b + 8;                     // 320
    float* sH = sPvloc + 320;                      // 544 + 1088 + 512

    unsigned sense = *((volatile unsigned*)&g_bar_sense);
    int tid = threadIdx.x;
    int half = tid >> 8, tl = tid & 255;
    int mt = blockIdx.x >> 5, jt = blockIdx.x & 31;
    int m0 = mt << 6, j0 = jt << 4;
    int gt = blockIdx.x * NTHR + tid;

    for (int i = gt; i < B * H; i += NBLK * NTHR) {
        g_h0a[i] = 0.f; g_h1a[i] = 0.f;
        g_h0h[0][i] = __float2bfloat16(0.f); g_h0l[0][i] = __float2bfloat16(0.f);
        g_h1h[0][i] = __float2bfloat16(0.f); g_h1l[0][i] = __float2bfloat16(0.f);
    }
    for (int i = gt; i < B * EMBD; i += NBLK * NTHR)
        g_embs[i] = p.emb[p.scenario[i >> 5] * EMBD + (i & 31)];
    {
        const float* bI[4] = { p.eb0i, p.eb1i, p.db0i, p.db1i };
        const float* bH[4] = { p.eb0h, p.eb1h, p.db0h, p.db1h };
        for (int idx = tid; idx < 384; idx += NTHR) {
            int ph = idx / 96, r = idx % 96, g = r >> 4, jj = r & 15;
            sBias[idx] = (g < 3) ? bI[ph][(g << 9) + j0 + jj] : bH[ph][((g - 3) << 9) + j0 + jj];
        }
        for (int idx = tid; idx < 240; idx += NTHR) {
            int g = idx / 80, r = idx % 80, jj = r / 5, q = r % 5;
            sPvw[idx] = p.dW0i[((g << 9) + j0 + jj) * 133 + 128 + q];
        }
        for (int idx = tid; idx < 640; idx += NTHR) sPv2W[idx] = p.fc2W[idx];
        if (tid < 5) sPv2b[tid] = p.fc2b[tid];
    }
    gsync(sense);   // embs visible

    // ---- one-time preconversions ----
    if (mt == 0) {   // W fragment file (32 CTAs cover all jt)
        const float* WP[8] = { p.eW0i, p.eW0h, p.eW1i, p.eW1h, p.dW0i, p.dW0h, p.dW1i, p.dW1h };
        const int LDW[8] = { 160, 512, 512, 512, 133, 512, 512, 512 };
        const int KS[8]  = { 12, 32, 32, 32, 8, 32, 32, 32 };
        const int KV[8]  = { 160, 512, 512, 512, 133, 512, 512, 512 };
        const int OFFm[8] = { 0, 2304, 8448, 14592, 20736, 22272, 28416, 34560 };
        uint4* base = g_wfrag + jt * WPJ;
        for (int m = 0; m < 8; m++) {
            const float* W = WP[m]; int ldw = LDW[m], Ks = KS[m], kv = KV[m];
            int tot = 6 * Ks * 32;
            for (int f = tid; f < tot; f += NTHR) {
                int lane = f & 31, rest = f >> 5;
                int ks = rest % Ks, nbg = rest / Ks;
                int nt = nbg * 8 + (lane >> 2);
                int grow = (nt >> 4) * 512 + jt * 16 + (nt & 15);
                int k0 = ks * 16 + ((lane & 3) << 1);
                const float* r = W + grow * ldw;
                float e0 = (k0 < kv) ? r[k0] : 0.f;
                float e1 = (k0 + 1 < kv) ? r[k0 + 1] : 0.f;
                float e8 = (k0 + 8 < kv) ? r[k0 + 8] : 0.f;
                float e9 = (k0 + 9 < kv) ? r[k0 + 9] : 0.f;
                base[OFFm[m] + (nbg * Ks + ks) * 32 + lane] =
                    make_uint4(pk2(e0, e1), pk2(e8, e9),
                               pk2(bflo(e0), bflo(e1)), pk2(bflo(e8), bflo(e9)));
            }
        }
    }
    // x inputs hi/lo split (all CTAs)
    for (size_t i = gt; i < (size_t)TE * B * 192; i += (size_t)NBLK * NTHR) {
        int t = (int)(i / (B * 192)); int r = (int)(i % (B * 192));
        int b = r / 192, k = r % 192;
        float v = (k < 128) ? p.x_cv[((size_t)b * TE + t) * 128 + k]
                            : (k < 160 ? g_embs[b * EMBD + (k - 128)] : 0.f);
        __nv_bfloat16 h = __float2bfloat16(v);
        g_exh[i] = h; g_exl[i] = __float2bfloat16(v - __bfloat162float(h));
    }
    for (size_t i = gt; i < (size_t)TT * B * 128; i += (size_t)NBLK * NTHR) {
        int t = (int)(i / (B * 128)); int r = (int)(i % (B * 128));
        int b = r >> 7, k = r & 127;
        float v = p.x_cv_target[((size_t)b * TT + t) * 128 + k];
        __nv_bfloat16 h = __float2bfloat16(v);
        g_dxh[i] = h; g_dxl[i] = __float2bfloat16(v - __bfloat162float(h));
    }
    gsync(sense);

    const uint4* WB = g_wfrag + jt * WPJ;
    float* h0buf[2] = { g_h0a, g_h0b };
    float* h1buf[2] = { g_h1a, g_h1b };

    // ---------------- encoder ----------------
    for (int t = 0; t < TE; t++) {
        int rd = t & 1, wr = rd ^ 1;
        if (!half) {
            gemm3(g_exh + (size_t)t * (B * 192), g_exl + (size_t)t * (B * 192), 192,
                  WB + 0, 12, 0, 12, m0, sA0h, sA0l, sW0, sGi, 1, tl);
            gemm3(g_h0h[rd], g_h0l[rd], 512, WB + 2304, 32, 0, 8, m0, sA0h, sA0l, sW0, sGh2, 1, tl);
        } else {
            gemm3(g_h0h[rd], g_h0l[rd], 512, WB + 2304, 32, 8, 24, m0, sA1h, sA1l, sW1, sGh, 2, tl);
        }
        __syncthreads();
        combineE0(sGi, sGh2, sGh, sBias, h0buf[rd], h0buf[wr], g_h0h[wr], g_h0l[wr], m0, j0, tid);
        gsync(sense);
        if (!half) gemm3(g_h0h[wr], g_h0l[wr], 512, WB + 8448, 32, 0, 32, m0, sA0h, sA0l, sW0, sGi, 1, tl);
        else       gemm3(g_h1h[rd], g_h1l[rd], 512, WB + 14592, 32, 0, 32, m0, sA1h, sA1l, sW1, sGh, 2, tl);
        __syncthreads();
        combine3(sGi, sGh, sBias + 96, h1buf[rd], h1buf[wr], g_h1h[wr], g_h1l[wr], m0, j0, tid);
        __syncthreads();
    }

    // ---------------- decoder ----------------
    // P0: h0(0) from gi0(0) + gh0(enc-final h0, in buf 0) + pv_init
    if (!half) gemm3(g_dxh, g_dxl, 128, WB + 20736, 8, 0, 8, m0, sA0h, sA0l, sW0, sGi, 1, tl);
    else       gemm3(g_h0h[0], g_h0l[0], 512, WB + 22272, 32, 0, 32, m0, sA1h, sA1l, sW1, sGh, 2, tl);
    __syncthreads();
    combineD0<false>(sGi, sGh, sBias + 192, sPvw, p.pv_init, h0buf[0], h0buf[1],
                     g_h0h[1], g_h0l[1], m0, j0, tid);
    gsync(sense);

    for (int t = 0; t < TT; t++) {
        int cur = (t + 1) & 1;
        float* h0cur = h0buf[cur];
        // D1: gi1 || gh1, then C1
        if (!half) gemm3(g_h0h[cur], g_h0l[cur], 512, WB + 28416, 32, 0, 32, m0, sA0h, sA0l, sW0, sGi, 1, tl);
        else       gemm3(g_h1h[t & 1], g_h1l[t & 1], 512, WB + 34560, 32, 0, 32, m0, sA1h, sA1l, sW1, sGh, 2, tl);
        __syncthreads();
        combine3(sGi, sGh, sBias + 288, h1buf[t & 1], h1buf[cur], g_h1h[cur], g_h1l[cur], m0, j0, tid);
        gsync(sense);
        // D2: half0: gh0(t+1) + gi0(t+1); half1: heads1(t)
        if (!half) {
            if (t + 1 < TT) {
                gemm3(g_h0h[cur], g_h0l[cur], 512, WB + 22272, 32, 0, 32, m0, sA0h, sA0l, sW0, sGh2, 1, tl);
                gemm3(g_dxh + (size_t)(t + 1) * (B * 128), g_dxl + (size_t)(t + 1) * (B * 128), 128,
                      WB + 20736, 8, 0, 8, m0, sA0h, sA0l, sW0, sGi, 1, tl);
            }
        } else {
            heads1h(sH, sH + 544, h1buf[cur], p.fc1W, p.fc1b, p.he1W, p.he1b, tl);
        }
        gsync(sense);
        // D3: pv local + heads2 + C0(t+1)
        pvcalc(sPvloc, sPv2W, sPv2b, m0, tid);
        __syncthreads();
        heads2(sH + 544 + 1088, t, p.fc2W, p.fc2b, p.he2W, p.he2b, p.out);
        if (t + 1 < TT)
            combineD0<true>(sGi, sGh2, sBias + 192, sPvw, sPvloc, h0cur, h0buf[t & 1],
                            g_h0h[t & 1], g_h0l[t & 1], m0, j0, tid);
        gsync(sense);
    }
}

extern "C" void kernel_launch(void* const* d_in, const int* in_sizes, int n_in,
                              void* d_out, int out_size) {
    (void)in_sizes; (void)n_in; (void)out_size;
    cudaFuncSetAttribute(gru_kernel, cudaFuncAttributeMaxDynamicSharedMemorySize, SMEM_BYTES);
    P p;
    p.x_cv        = (const float*)d_in[0];
    p.x_cv_target = (const float*)d_in[1];
    p.pv_init     = (const float*)d_in[2];
    p.scenario    = (const int*)d_in[3];
    p.emb         = (const float*)d_in[4];
    p.eW0i = (const float*)d_in[5];  p.eW0h = (const float*)d_in[6];
    p.eb0i = (const float*)d_in[7];  p.eb0h = (const float*)d_in[8];
    p.eW1i = (const float*)d_in[9];  p.eW1h = (const float*)d_in[10];
    p.eb1i = (const float*)d_in[11]; p.eb1h = (const float*)d_in[12];
    p.dW0i = (const float*)d_in[13]; p.dW0h = (const float*)d_in[14];
    p.db0i = (const float*)d_in[15]; p.db0h = (const float*)d_in[16];
    p.dW1i = (const float*)d_in[17]; p.dW1h = (const float*)d_in[18];
    p.db1i = (const float*)d_in[19]; p.db1h = (const float*)d_in[20];
    p.fc1W = (const float*)d_in[21]; p.fc1b = (const float*)d_in[22];
    p.fc2W = (const float*)d_in[23]; p.fc2b = (const float*)d_in[24];
    p.he1W = (const float*)d_in[25]; p.he1b = (const float*)d_in[26];
    p.he2W = (const float*)d_in[27]; p.he2b = (const float*)d_in[28];
    p.out  = (float*)d_out;
    gru_kernel<<<NBLK, NTHR, SMEM_BYTES>>>(p);
}